// round 1
// baseline (speedup 1.0000x reference)
#include <cuda_runtime.h>
#include <cstdint>

// Problem constants
#define NN   4096   // nodes
#define FIN  512    // in features
#define HH   8      // heads
#define DD   64     // dim per head
#define HD   512    // H*D

// Scratch (device globals; no allocation allowed)
__device__ float g_mx[NN * HD];      // projected features [n][h*64+d]  (8 MB)
__device__ float g_Wf[FIN * HD];     // repacked W: [f][h*64+d]          (1 MB)
__device__ float g_t [HH * NN];      // t[h][n] = mx[n,h,:] . a_dst[h]   (128 KB)

// ---------------------------------------------------------------------------
// Kernel 0: repack W [H][F][D] -> Wf [F][H*D]
// ---------------------------------------------------------------------------
__global__ void repack_kernel(const float* __restrict__ W, float* __restrict__ Wf) {
    int i = blockIdx.x * blockDim.x + threadIdx.x;
    if (i < FIN * HD) {
        int f = i >> 9;          // / 512
        int c = i & 511;
        int h = c >> 6;
        int d = c & 63;
        Wf[i] = W[h * FIN * DD + f * DD + d];
    }
}

// ---------------------------------------------------------------------------
// Kernel 1: GEMM  mx[4096x512] = x[4096x512] @ Wf[512x512]   (fp32 SIMT)
// BM=64, BN=64, BK=32, 256 threads, 4x4 per-thread tile
// ---------------------------------------------------------------------------
#define BM 64
#define BN 64
#define BK 32
__global__ __launch_bounds__(256) void gemm_kernel(
    const float* __restrict__ A, const float* __restrict__ B, float* __restrict__ C)
{
    __shared__ float As[BK][BM];
    __shared__ float Bs[BK][BN];

    const int tid = threadIdx.x;
    const int tx = tid & 15;        // 0..15
    const int ty = tid >> 4;        // 0..15
    const int rowBase = blockIdx.y * BM;
    const int colBase = blockIdx.x * BN;

    // loader coords
    const int arow = tid >> 3;            // 0..31
    const int acol = (tid & 7) * 4;       // 0..28
    const int brow = tid >> 4;            // 0..15
    const int bcol = (tid & 15) * 4;      // 0..60

    float acc[4][4];
#pragma unroll
    for (int i = 0; i < 4; i++)
#pragma unroll
        for (int j = 0; j < 4; j++) acc[i][j] = 0.f;

    for (int k0 = 0; k0 < FIN; k0 += BK) {
#pragma unroll
        for (int r = 0; r < 2; r++) {
            int ar = arow + r * 32;
            float4 v = *(const float4*)&A[(size_t)(rowBase + ar) * FIN + k0 + acol];
            As[acol + 0][ar] = v.x;
            As[acol + 1][ar] = v.y;
            As[acol + 2][ar] = v.z;
            As[acol + 3][ar] = v.w;
        }
#pragma unroll
        for (int r = 0; r < 2; r++) {
            int br = brow + r * 16;
            *(float4*)&Bs[br][bcol] =
                *(const float4*)&B[(size_t)(k0 + br) * HD + colBase + bcol];
        }
        __syncthreads();

#pragma unroll
        for (int kk = 0; kk < BK; kk++) {
            float4 a4 = *(const float4*)&As[kk][ty * 4];
            float4 b4 = *(const float4*)&Bs[kk][tx * 4];
            float a[4] = {a4.x, a4.y, a4.z, a4.w};
            float b[4] = {b4.x, b4.y, b4.z, b4.w};
#pragma unroll
            for (int i = 0; i < 4; i++)
#pragma unroll
                for (int j = 0; j < 4; j++)
                    acc[i][j] = fmaf(a[i], b[j], acc[i][j]);
        }
        __syncthreads();
    }

#pragma unroll
    for (int i = 0; i < 4; i++) {
        int row = rowBase + ty * 4 + i;
        float4 v = make_float4(acc[i][0], acc[i][1], acc[i][2], acc[i][3]);
        *(float4*)&C[(size_t)row * HD + colBase + tx * 4] = v;
    }
}

// ---------------------------------------------------------------------------
// Kernel 2: t[h][n] = sum_d mx[n][h*64+d] * a_dst[h*64+d]
// One warp per node.
// ---------------------------------------------------------------------------
__global__ void t_kernel(const float* __restrict__ mx, const float* __restrict__ a_dst,
                         float* __restrict__ t)
{
    int gwarp = (blockIdx.x * blockDim.x + threadIdx.x) >> 5;
    int lane = threadIdx.x & 31;
    if (gwarp >= NN) return;
    const float* r = mx + (size_t)gwarp * HD;
#pragma unroll
    for (int h = 0; h < HH; h++) {
        float v = r[h * 64 + lane]       * a_dst[h * 64 + lane]
                + r[h * 64 + 32 + lane]  * a_dst[h * 64 + 32 + lane];
#pragma unroll
        for (int off = 16; off; off >>= 1)
            v += __shfl_xor_sync(0xffffffffu, v, off);
        if (lane == 0) t[h * NN + gwarp] = v;
    }
}

// ---------------------------------------------------------------------------
// Kernel 3: sparse attention.
// One block (512 threads) per node:
//   - ordered neighbor compaction (prefix scan -> deterministic)
//   - per-head max over neighbors
//   - chunked: weights w[j][h] = exp(t[h][j]-m[h]); denominator; weighted sum
// ---------------------------------------------------------------------------
__global__ __launch_bounds__(512) void attn_kernel(
    const float* __restrict__ adj, const float* __restrict__ mx,
    const float* __restrict__ t, float* __restrict__ out)
{
    const int node = blockIdx.x;
    const int tid = threadIdx.x;          // 0..511

    __shared__ int   sInd[NN];            // neighbor indices (16 KB)
    __shared__ float sW[512 * 8];         // chunk weights [j][h] (16 KB)
    __shared__ int   sScan[512];
    __shared__ float sRed[16][8];
    __shared__ float sMax[8];
    __shared__ float sS[8];

    // ---- 1. ordered compaction of adj row ----
    const float* row = adj + (size_t)node * NN;
    float4 v0 = *(const float4*)&row[tid * 8];
    float4 v1 = *(const float4*)&row[tid * 8 + 4];
    float av[8] = {v0.x, v0.y, v0.z, v0.w, v1.x, v1.y, v1.z, v1.w};
    int cnt = 0;
#pragma unroll
    for (int i = 0; i < 8; i++) cnt += (av[i] > 0.f);

    sScan[tid] = cnt;
    __syncthreads();
    for (int off = 1; off < 512; off <<= 1) {
        int v = sScan[tid];
        if (tid >= off) v += sScan[tid - off];
        __syncthreads();
        sScan[tid] = v;
        __syncthreads();
    }
    const int K = sScan[511];
    int pos = sScan[tid] - cnt;
#pragma unroll
    for (int i = 0; i < 8; i++)
        if (av[i] > 0.f) sInd[pos++] = tid * 8 + i;
    __syncthreads();

    // ---- 2. per-head max over neighbors ----
    float m[8];
#pragma unroll
    for (int h = 0; h < 8; h++) m[h] = -3.4e38f;
    for (int j = tid; j < K; j += 512) {
        int jj = sInd[j];
#pragma unroll
        for (int h = 0; h < 8; h++) m[h] = fmaxf(m[h], t[h * NN + jj]);
    }
#pragma unroll
    for (int off = 16; off; off >>= 1)
#pragma unroll
        for (int h = 0; h < 8; h++)
            m[h] = fmaxf(m[h], __shfl_xor_sync(0xffffffffu, m[h], off));
    const int warp = tid >> 5, lane = tid & 31;
    if (lane == 0)
#pragma unroll
        for (int h = 0; h < 8; h++) sRed[warp][h] = m[h];
    __syncthreads();
    if (tid < 8) {
        float mm = -3.4e38f;
#pragma unroll
        for (int w = 0; w < 16; w++) mm = fmaxf(mm, sRed[w][tid]);
        sMax[tid] = mm;
        sS[tid] = 0.f;
    }
    __syncthreads();

    // ---- 3. chunked softmax-weighted gather ----
    const int h = tid >> 6;        // 0..7
    const int col = tid;           // == h*64 + d
    float acc = 0.f;

    for (int base = 0; base < K; base += 512) {
        int lim = min(512, K - base);
        for (int idx = tid; idx < lim * 8; idx += 512) {
            int jj = idx >> 3, hh = idx & 7;
            sW[idx] = __expf(t[hh * NN + sInd[base + jj]] - sMax[hh]);
        }
        __syncthreads();
        if (tid < 8) {
            float s = 0.f;
            for (int jj = 0; jj < lim; jj++) s += sW[jj * 8 + tid];
            sS[tid] += s;
        }
        for (int jj = 0; jj < lim; jj++) {
            acc = fmaf(sW[jj * 8 + h],
                       mx[(size_t)sInd[base + jj] * HD + col], acc);
        }
        __syncthreads();
    }

    out[(size_t)node * HD + col] = acc / sS[h];
}

// ---------------------------------------------------------------------------
// Launch
// inputs: 0:x [4096,512]  1:adj [4096,4096]  2:W [8,512,64]
//         3:a_origin [8,64] (unused — cancels in row softmax)  4:a_dst [8,64]
// output: [4096, 512] float32
// ---------------------------------------------------------------------------
extern "C" void kernel_launch(void* const* d_in, const int* in_sizes, int n_in,
                              void* d_out, int out_size)
{
    const float* x     = (const float*)d_in[0];
    const float* adj   = (const float*)d_in[1];
    const float* W     = (const float*)d_in[2];
    const float* a_dst = (const float*)d_in[4];
    float* out = (float*)d_out;

    float* mx; cudaGetSymbolAddress((void**)&mx, g_mx);
    float* Wf; cudaGetSymbolAddress((void**)&Wf, g_Wf);
    float* tb; cudaGetSymbolAddress((void**)&tb, g_t);

    repack_kernel<<<(FIN * HD + 255) / 256, 256>>>(W, Wf);

    dim3 ggrid(HD / BN, NN / BM);
    gemm_kernel<<<ggrid, 256>>>(x, Wf, mx);

    t_kernel<<<(NN * 32 + 255) / 256, 256>>>(mx, a_dst, tb);

    attn_kernel<<<NN, 512>>>(adj, mx, tb, out);
}

// round 5
// speedup vs baseline: 1.5101x; 1.5101x over previous
#include <cuda_runtime.h>
#include <cstdint>

#define NN   4096
#define FIN  512
#define HH   8
#define DD   64
#define HD   512

// Scratch
__device__ float g_mx[NN * HD];   // projected features, then pre-scaled in place (8 MB)
__device__ float g_Wf[FIN * HD];  // repacked W [f][h*64+d]
__device__ float g_ez[NN * HH];   // exp(t) per node/head

typedef unsigned long long u64;

__device__ __forceinline__ u64 pack2(float x, float y) {
    u64 r; asm("mov.b64 %0, {%1, %2};" : "=l"(r) : "f"(x), "f"(y)); return r;
}
__device__ __forceinline__ void unpack2(float& x, float& y, u64 v) {
    asm("mov.b64 {%0, %1}, %2;" : "=f"(x), "=f"(y) : "l"(v));
}
#define FFMA2(d, a, b) asm("fma.rn.f32x2 %0, %1, %2, %0;" : "+l"(d) : "l"(a), "l"(b))

// ---------------------------------------------------------------------------
// Kernel 0: repack W [H][F][D] -> Wf [F][H*D]
// ---------------------------------------------------------------------------
__global__ void repack_kernel(const float* __restrict__ W, float* __restrict__ Wf) {
    int i = blockIdx.x * blockDim.x + threadIdx.x;
    if (i < FIN * HD) {
        int f = i >> 9, c = i & 511, h = c >> 6, d = c & 63;
        Wf[i] = W[h * FIN * DD + f * DD + d];
    }
}

// ---------------------------------------------------------------------------
// Kernel 1: GEMM mx = x @ Wf using packed fma.rn.f32x2
// BM=64, BN=128, BK=16, 256 threads, per-thread 8 rows x 4 cols
// ---------------------------------------------------------------------------
#define BM 64
#define BN 128
#define BK 16
__global__ __launch_bounds__(256) void gemm_kernel(
    const float* __restrict__ A, const float* __restrict__ B, float* __restrict__ C)
{
    __shared__ float As[BK][BM];   // transposed
    __shared__ float Bs[BK][BN];

    const int tid = threadIdx.x;
    const int tx = tid & 31;
    const int ty = tid >> 5;
    const int rowBase = blockIdx.y * BM;
    const int colBase = blockIdx.x * BN;

    const int arow = tid >> 2;            // 0..63
    const int ak   = (tid & 3) * 4;       // 0,4,8,12
    const int bk   = tid >> 5;            // 0..7
    const int bcol = (tid & 31) * 4;

    u64 acc[4][4];
#pragma unroll
    for (int p = 0; p < 4; p++)
#pragma unroll
        for (int j = 0; j < 4; j++) acc[p][j] = pack2(0.f, 0.f);

    for (int k0 = 0; k0 < FIN; k0 += BK) {
        {
            float4 v = *(const float4*)&A[(size_t)(rowBase + arow) * FIN + k0 + ak];
            As[ak + 0][arow] = v.x; As[ak + 1][arow] = v.y;
            As[ak + 2][arow] = v.z; As[ak + 3][arow] = v.w;
            *(float4*)&Bs[bk][bcol]     = *(const float4*)&B[(size_t)(k0 + bk) * HD + colBase + bcol];
            *(float4*)&Bs[bk + 8][bcol] = *(const float4*)&B[(size_t)(k0 + bk + 8) * HD + colBase + bcol];
        }
        __syncthreads();

#pragma unroll
        for (int kk = 0; kk < BK; kk++) {
            ulonglong2 aa0 = *(const ulonglong2*)&As[kk][ty * 8];
            ulonglong2 aa1 = *(const ulonglong2*)&As[kk][ty * 8 + 4];
            u64 aa[4] = {aa0.x, aa0.y, aa1.x, aa1.y};
            float4 b = *(const float4*)&Bs[kk][tx * 4];
            u64 bb[4] = {pack2(b.x, b.x), pack2(b.y, b.y), pack2(b.z, b.z), pack2(b.w, b.w)};
#pragma unroll
            for (int p = 0; p < 4; p++)
#pragma unroll
                for (int j = 0; j < 4; j++)
                    FFMA2(acc[p][j], aa[p], bb[j]);
        }
        __syncthreads();
    }

#pragma unroll
    for (int p = 0; p < 4; p++) {
        float lo[4], hi[4];
#pragma unroll
        for (int j = 0; j < 4; j++) unpack2(lo[j], hi[j], acc[p][j]);
        int r0 = rowBase + ty * 8 + p * 2;
        *(float4*)&C[(size_t)r0 * HD + colBase + tx * 4]       = make_float4(lo[0], lo[1], lo[2], lo[3]);
        *(float4*)&C[(size_t)(r0 + 1) * HD + colBase + tx * 4] = make_float4(hi[0], hi[1], hi[2], hi[3]);
    }
}

// ---------------------------------------------------------------------------
// Kernel 2: prep — t[h]=mx[n,h,:].a_dst[h]; e=exp(t); mx *= e (in place)
// One warp per node.
// ---------------------------------------------------------------------------
__global__ void prep_kernel(float* __restrict__ mx, const float* __restrict__ a_dst,
                            float* __restrict__ ez)
{
    int node = (blockIdx.x * blockDim.x + threadIdx.x) >> 5;
    int lane = threadIdx.x & 31;
    if (node >= NN) return;
    float* r = mx + (size_t)node * HD;
#pragma unroll
    for (int h = 0; h < HH; h++) {
        float m0 = r[h * 64 + lane];
        float m1 = r[h * 64 + 32 + lane];
        float v = m0 * a_dst[h * 64 + lane] + m1 * a_dst[h * 64 + 32 + lane];
#pragma unroll
        for (int off = 16; off; off >>= 1)
            v += __shfl_xor_sync(0xffffffffu, v, off);
        float e = __expf(v);
        r[h * 64 + lane]      = m0 * e;
        r[h * 64 + 32 + lane] = m1 * e;
        if (lane == 0) ez[node * HH + h] = e;
    }
}

// ---------------------------------------------------------------------------
// Kernel 3: sparse attention gather.
// One block (256 threads) per node. ALL __syncthreads() are in uniform
// control flow (the R2 deadlock was an intra-warp divergent barrier).
// ---------------------------------------------------------------------------
__global__ __launch_bounds__(256) void attn_kernel(
    const float* __restrict__ adj, const float* __restrict__ Y,
    const float* __restrict__ ez, float* __restrict__ out)
{
    const int node = blockIdx.x;
    const int tid = threadIdx.x;
    const int lane = tid & 31;
    const int warp = tid >> 5;

    __shared__ int   sInd[NN];       // 16 KB worst case
    __shared__ int   sWS[8];
    __shared__ int   sWE[8];
    __shared__ int   sK;
    __shared__ float sDen[8];

    // ---- compaction: thread t owns cols [t*16, t*16+16) ----
    const float* row = adj + (size_t)node * NN;
    float av[16];
#pragma unroll
    for (int q = 0; q < 4; q++) {
        float4 v = *(const float4*)&row[tid * 16 + q * 4];
        av[q * 4 + 0] = v.x; av[q * 4 + 1] = v.y; av[q * 4 + 2] = v.z; av[q * 4 + 3] = v.w;
    }
    int cnt = 0;
#pragma unroll
    for (int i = 0; i < 16; i++) cnt += (av[i] > 0.f);

    int incl = cnt;
#pragma unroll
    for (int off = 1; off < 32; off <<= 1) {
        int v = __shfl_up_sync(0xffffffffu, incl, off);
        if (lane >= off) incl += v;
    }
    if (lane == 31) sWS[warp] = incl;
    __syncthreads();                       // uniform
    if (tid < 8) {
        int v = sWS[tid];
        int s = v;
#pragma unroll
        for (int off = 1; off < 8; off <<= 1) {
            int u = __shfl_up_sync(0xffu, s, off);
            if (tid >= off) s += u;
        }
        sWE[tid] = s - v;
        if (tid == 7) sK = s;
    }
    __syncthreads();                       // uniform

    int pos = sWE[warp] + incl - cnt;
#pragma unroll
    for (int i = 0; i < 16; i++)
        if (av[i] > 0.f) sInd[pos++] = tid * 16 + i;
    __syncthreads();                       // uniform

    const int K = sK;

    // ---- gather (no barriers inside branches) ----
    float4 acc = make_float4(0.f, 0.f, 0.f, 0.f);
    if (tid < 128) {
        const int col = tid * 4;
        int j = 0;
        for (; j + 4 <= K; j += 4) {
            int i0 = sInd[j], i1 = sInd[j + 1], i2 = sInd[j + 2], i3 = sInd[j + 3];
            float4 v0 = *(const float4*)&Y[(size_t)i0 * HD + col];
            float4 v1 = *(const float4*)&Y[(size_t)i1 * HD + col];
            float4 v2 = *(const float4*)&Y[(size_t)i2 * HD + col];
            float4 v3 = *(const float4*)&Y[(size_t)i3 * HD + col];
            acc.x += v0.x + v1.x + v2.x + v3.x;
            acc.y += v0.y + v1.y + v2.y + v3.y;
            acc.z += v0.z + v1.z + v2.z + v3.z;
            acc.w += v0.w + v1.w + v2.w + v3.w;
        }
        for (; j < K; j++) {
            float4 v = *(const float4*)&Y[(size_t)sInd[j] * HD + col];
            acc.x += v.x; acc.y += v.y; acc.z += v.z; acc.w += v.w;
        }
    } else if (tid < 136) {
        const int h = tid - 128;
        float d = 0.f;
        int j = 0;
        for (; j + 4 <= K; j += 4) {
            float d0 = ez[sInd[j] * HH + h];
            float d1 = ez[sInd[j + 1] * HH + h];
            float d2 = ez[sInd[j + 2] * HH + h];
            float d3 = ez[sInd[j + 3] * HH + h];
            d += d0 + d1 + d2 + d3;
        }
        for (; j < K; j++) d += ez[sInd[j] * HH + h];
        sDen[h] = d;
    }
    __syncthreads();                       // uniform — single barrier for everyone

    if (tid < 128) {
        const int col = tid * 4;
        float inv = 1.f / sDen[tid >> 4];
        acc.x *= inv; acc.y *= inv; acc.z *= inv; acc.w *= inv;
        *(float4*)&out[(size_t)node * HD + col] = acc;
    }
}

// ---------------------------------------------------------------------------
// inputs: 0:x  1:adj  2:W  3:a_origin (cancels in softmax)  4:a_dst
// ---------------------------------------------------------------------------
extern "C" void kernel_launch(void* const* d_in, const int* in_sizes, int n_in,
                              void* d_out, int out_size)
{
    const float* x     = (const float*)d_in[0];
    const float* adj   = (const float*)d_in[1];
    const float* W     = (const float*)d_in[2];
    const float* a_dst = (const float*)d_in[4];
    float* out = (float*)d_out;

    float* mx; cudaGetSymbolAddress((void**)&mx, g_mx);
    float* Wf; cudaGetSymbolAddress((void**)&Wf, g_Wf);
    float* ez; cudaGetSymbolAddress((void**)&ez, g_ez);

    repack_kernel<<<(FIN * HD + 255) / 256, 256>>>(W, Wf);

    dim3 ggrid(HD / BN, NN / BM);   // (4, 64) = 256 blocks
    gemm_kernel<<<ggrid, 256>>>(x, Wf, mx);

    prep_kernel<<<(NN * 32 + 255) / 256, 256>>>(mx, a_dst, ez);

    attn_kernel<<<NN, 256>>>(adj, mx, ez, out);
}

// round 8
// speedup vs baseline: 1.9329x; 1.2800x over previous
#include <cuda_runtime.h>
#include <cuda_bf16.h>
#include <cstdint>

#define NN   4096
#define FIN  512
#define HH   8
#define DD   64
#define HD   512

// Scratch (device globals)
__device__ float g_mx[NN * HD];          // projected features -> pre-scaled Y (8 MB)
__device__ float g_ez[NN * HH];          // exp(t)
__device__ __nv_bfloat16 g_xh[NN * FIN]; // x hi  (4 MB)
__device__ __nv_bfloat16 g_xl[NN * FIN]; // x lo  (4 MB)
__device__ __nv_bfloat16 g_wh[HD * FIN]; // W^T hi [n][k] (512 KB)
__device__ __nv_bfloat16 g_wl[HD * FIN]; // W^T lo

__device__ __forceinline__ uint32_t smem_u32(const void* p) {
    uint32_t a;
    asm("{ .reg .u64 t; cvta.to.shared.u64 t, %1; cvt.u32.u64 %0, t; }" : "=r"(a) : "l"(p));
    return a;
}
__device__ __forceinline__ void ldsm4(uint32_t* r, uint32_t addr) {
    asm volatile("ldmatrix.sync.aligned.m8n8.x4.shared.b16 {%0,%1,%2,%3}, [%4];"
                 : "=r"(r[0]), "=r"(r[1]), "=r"(r[2]), "=r"(r[3]) : "r"(addr));
}
__device__ __forceinline__ void mma16816(float* c, const uint32_t* a, const uint32_t* b) {
    asm volatile(
        "mma.sync.aligned.m16n8k16.row.col.f32.bf16.bf16.f32 "
        "{%0,%1,%2,%3}, {%4,%5,%6,%7}, {%8,%9}, {%0,%1,%2,%3};"
        : "+f"(c[0]), "+f"(c[1]), "+f"(c[2]), "+f"(c[3])
        : "r"(a[0]), "r"(a[1]), "r"(a[2]), "r"(a[3]), "r"(b[0]), "r"(b[1]));
}

// ---------------------------------------------------------------------------
// Kernel 0a: split x into bf16 hi/lo
// ---------------------------------------------------------------------------
__global__ void conv_x_kernel(const float* __restrict__ x,
                              __nv_bfloat16* __restrict__ xh, __nv_bfloat16* __restrict__ xl) {
    int i = (blockIdx.x * blockDim.x + threadIdx.x) * 4;
    if (i >= NN * FIN) return;
    float4 v = *(const float4*)(x + i);
    float f[4] = {v.x, v.y, v.z, v.w};
#pragma unroll
    for (int j = 0; j < 4; j++) {
        __nv_bfloat16 h = __float2bfloat16(f[j]);
        xh[i + j] = h;
        xl[i + j] = __float2bfloat16(f[j] - __bfloat162float(h));
    }
}

// ---------------------------------------------------------------------------
// Kernel 0b: W [H][F][D] -> W^T [n=h*64+d][k=f] bf16 hi/lo
// ---------------------------------------------------------------------------
__global__ void conv_w_kernel(const float* __restrict__ W,
                              __nv_bfloat16* __restrict__ wh, __nv_bfloat16* __restrict__ wl) {
    int i = blockIdx.x * blockDim.x + threadIdx.x;
    if (i >= HD * FIN) return;
    int n = i >> 9, k = i & 511;
    int h = n >> 6, d = n & 63;
    float w = W[h * FIN * DD + k * DD + d];
    __nv_bfloat16 hi = __float2bfloat16(w);
    wh[i] = hi;
    wl[i] = __float2bfloat16(w - __bfloat162float(hi));
}

// ---------------------------------------------------------------------------
// Kernel 1: bf16-split GEMM on mma.sync.m16n8k16 (HMMA), fp32 accumulate.
// CTA tile 128x64, 8 warps (4M x 2N), warp tile 32x32, BK=32, double-buffered.
// ---------------------------------------------------------------------------
#define SROW 40                              // padded row length in bf16 elems
#define A_BYTES (128 * SROW * 2)             // 10240
#define B_BYTES (64 * SROW * 2)              // 5120
#define STAGE_BYTES (2 * A_BYTES + 2 * B_BYTES)  // 30720
#define GSMEM (2 * STAGE_BYTES)              // 61440
// offsets within a stage
#define SOFF_AH 0
#define SOFF_AL A_BYTES
#define SOFF_BH (2 * A_BYTES)
#define SOFF_BL (2 * A_BYTES + B_BYTES)

__global__ __launch_bounds__(256) void gemm_mma_kernel(
    const __nv_bfloat16* __restrict__ xh, const __nv_bfloat16* __restrict__ xl,
    const __nv_bfloat16* __restrict__ wh, const __nv_bfloat16* __restrict__ wl,
    float* __restrict__ C)
{
    extern __shared__ char sm[];
    const uint32_t sb = smem_u32(sm);
    const int tid = threadIdx.x;
    const int lane = tid & 31;
    const int warp = tid >> 5;
    const int wm = warp >> 1;        // 0..3
    const int wn = warp & 1;         // 0..1
    const int rowBase = blockIdx.y * 128;
    const int colBase = blockIdx.x * 64;

    // global-load coords
    const int ar = tid >> 1;                 // 0..127
    const int ak = (tid & 1) * 16;           // 0 or 16
    const int br = tid >> 2;                 // 0..63
    const int bk = (tid & 3) * 8;            // 0,8,16,24

    const __nv_bfloat16* gAh = xh + (size_t)(rowBase + ar) * FIN + ak;
    const __nv_bfloat16* gAl = xl + (size_t)(rowBase + ar) * FIN + ak;
    const __nv_bfloat16* gBh = wh + (size_t)(colBase + br) * FIN + bk;
    const __nv_bfloat16* gBl = wl + (size_t)(colBase + br) * FIN + bk;

    // smem store addresses (byte offsets within a stage)
    const uint32_t sAoff = (uint32_t)(ar * SROW + ak) * 2;
    const uint32_t sBoff = (uint32_t)(br * SROW + bk) * 2;

    float acc[2][4][4];
#pragma unroll
    for (int m = 0; m < 2; m++)
#pragma unroll
        for (int nb = 0; nb < 4; nb++)
#pragma unroll
            for (int q = 0; q < 4; q++) acc[m][nb][q] = 0.f;

    // ldmatrix lane addressing pieces
    const int t  = lane >> 3;       // tile index 0..3
    const int tr = lane & 7;        // row within tile
    // A-frag: mOff=(t&1)*8, kOff=(t>>1)*8 ; B-frag: nOff=(t>>1)*8, kOff=(t&1)*8
    const int a_mOff = (t & 1) * 8, a_kOff = (t >> 1) * 8;
    const int b_nOff = (t >> 1) * 8, b_kOff = (t & 1) * 8;

    // ---- prologue: fill stage 0 ----
    {
        char* st = sm;
        *(uint4*)(st + SOFF_AH + sAoff)      = *(const uint4*)(gAh);
        *(uint4*)(st + SOFF_AH + sAoff + 16) = *(const uint4*)(gAh + 8);
        *(uint4*)(st + SOFF_AL + sAoff)      = *(const uint4*)(gAl);
        *(uint4*)(st + SOFF_AL + sAoff + 16) = *(const uint4*)(gAl + 8);
        *(uint4*)(st + SOFF_BH + sBoff)      = *(const uint4*)(gBh);
        *(uint4*)(st + SOFF_BL + sBoff)      = *(const uint4*)(gBl);
    }
    __syncthreads();

    for (int it = 0; it < 16; it++) {
        const int cur = it & 1;
        // prefetch next chunk into registers
        uint4 pA0, pA1, pAl0, pAl1, pB, pBl;
        if (it < 15) {
            int k0 = (it + 1) * 32;
            pA0  = *(const uint4*)(gAh + k0);
            pA1  = *(const uint4*)(gAh + k0 + 8);
            pAl0 = *(const uint4*)(gAl + k0);
            pAl1 = *(const uint4*)(gAl + k0 + 8);
            pB   = *(const uint4*)(gBh + k0);
            pBl  = *(const uint4*)(gBl + k0);
        }

        const uint32_t base = sb + (uint32_t)cur * STAGE_BYTES;
#pragma unroll
        for (int ks = 0; ks < 2; ks++) {
            uint32_t ah[2][4], al[2][4], bhf[4][2], blf[4][2];
#pragma unroll
            for (int m = 0; m < 2; m++) {
                uint32_t rowA = (uint32_t)(wm * 32 + m * 16 + a_mOff + tr);
                uint32_t colA = (uint32_t)(ks * 16 + a_kOff);
                uint32_t ad = base + (rowA * SROW + colA) * 2;
                ldsm4(ah[m], ad + SOFF_AH);
                ldsm4(al[m], ad + SOFF_AL);
            }
#pragma unroll
            for (int nb16 = 0; nb16 < 2; nb16++) {
                uint32_t rowB = (uint32_t)(wn * 32 + nb16 * 16 + b_nOff + tr);
                uint32_t colB = (uint32_t)(ks * 16 + b_kOff);
                uint32_t bd = base + (rowB * SROW + colB) * 2;
                uint32_t rh[4], rl[4];
                ldsm4(rh, bd + SOFF_BH);
                ldsm4(rl, bd + SOFF_BL);
                bhf[nb16 * 2 + 0][0] = rh[0]; bhf[nb16 * 2 + 0][1] = rh[1];
                bhf[nb16 * 2 + 1][0] = rh[2]; bhf[nb16 * 2 + 1][1] = rh[3];
                blf[nb16 * 2 + 0][0] = rl[0]; blf[nb16 * 2 + 0][1] = rl[1];
                blf[nb16 * 2 + 1][0] = rl[2]; blf[nb16 * 2 + 1][1] = rl[3];
            }
#pragma unroll
            for (int m = 0; m < 2; m++)
#pragma unroll
                for (int nb = 0; nb < 4; nb++) {
                    mma16816(acc[m][nb], ah[m], bhf[nb]);
                    mma16816(acc[m][nb], ah[m], blf[nb]);
                    mma16816(acc[m][nb], al[m], bhf[nb]);
                }
        }
        __syncthreads();           // everyone done reading stage `cur`

        if (it < 15) {
            char* st = sm + ((it + 1) & 1) * STAGE_BYTES;
            *(uint4*)(st + SOFF_AH + sAoff)      = pA0;
            *(uint4*)(st + SOFF_AH + sAoff + 16) = pA1;
            *(uint4*)(st + SOFF_AL + sAoff)      = pAl0;
            *(uint4*)(st + SOFF_AL + sAoff + 16) = pAl1;
            *(uint4*)(st + SOFF_BH + sBoff)      = pB;
            *(uint4*)(st + SOFF_BL + sBoff)      = pBl;
            __syncthreads();
        }
    }

    // ---- epilogue ----
    const int g = lane >> 2, tg = lane & 3;
#pragma unroll
    for (int m = 0; m < 2; m++) {
        int row0 = rowBase + wm * 32 + m * 16 + g;
#pragma unroll
        for (int nb = 0; nb < 4; nb++) {
            int col = colBase + wn * 32 + nb * 8 + 2 * tg;
            *(float2*)&C[(size_t)row0 * HD + col]       = make_float2(acc[m][nb][0], acc[m][nb][1]);
            *(float2*)&C[(size_t)(row0 + 8) * HD + col] = make_float2(acc[m][nb][2], acc[m][nb][3]);
        }
    }
}

// ---------------------------------------------------------------------------
// Kernel 2: prep — t[h]=mx[n,h,:].a_dst[h]; e=exp(t); mx *= e in place
// ---------------------------------------------------------------------------
__global__ void prep_kernel(float* __restrict__ mx, const float* __restrict__ a_dst,
                            float* __restrict__ ez)
{
    int node = (blockIdx.x * blockDim.x + threadIdx.x) >> 5;
    int lane = threadIdx.x & 31;
    if (node >= NN) return;
    float* r = mx + (size_t)node * HD;
#pragma unroll
    for (int h = 0; h < HH; h++) {
        float m0 = r[h * 64 + lane];
        float m1 = r[h * 64 + 32 + lane];
        float v = m0 * a_dst[h * 64 + lane] + m1 * a_dst[h * 64 + 32 + lane];
#pragma unroll
        for (int off = 16; off; off >>= 1)
            v += __shfl_xor_sync(0xffffffffu, v, off);
        float e = __expf(v);
        r[h * 64 + lane]      = m0 * e;
        r[h * 64 + 32 + lane] = m1 * e;
        if (lane == 0) ez[node * HH + h] = e;
    }
}

// ---------------------------------------------------------------------------
// Kernel 3: sparse attention gather (barriers all uniform).
// ---------------------------------------------------------------------------
__global__ __launch_bounds__(256) void attn_kernel(
    const float* __restrict__ adj, const float* __restrict__ Y,
    const float* __restrict__ ez, float* __restrict__ out)
{
    const int node = blockIdx.x;
    const int tid = threadIdx.x;
    const int lane = tid & 31;
    const int warp = tid >> 5;

    __shared__ int   sInd[NN];
    __shared__ int   sWS[8];
    __shared__ int   sWE[8];
    __shared__ int   sK;
    __shared__ float sDen[8];

    const float* row = adj + (size_t)node * NN;
    float av[16];
#pragma unroll
    for (int q = 0; q < 4; q++) {
        float4 v = *(const float4*)&row[tid * 16 + q * 4];
        av[q * 4 + 0] = v.x; av[q * 4 + 1] = v.y; av[q * 4 + 2] = v.z; av[q * 4 + 3] = v.w;
    }
    int cnt = 0;
#pragma unroll
    for (int i = 0; i < 16; i++) cnt += (av[i] > 0.f);

    int incl = cnt;
#pragma unroll
    for (int off = 1; off < 32; off <<= 1) {
        int v = __shfl_up_sync(0xffffffffu, incl, off);
        if (lane >= off) incl += v;
    }
    if (lane == 31) sWS[warp] = incl;
    __syncthreads();
    if (tid < 8) {
        int v = sWS[tid];
        int s = v;
#pragma unroll
        for (int off = 1; off < 8; off <<= 1) {
            int u = __shfl_up_sync(0xffu, s, off);
            if (tid >= off) s += u;
        }
        sWE[tid] = s - v;
        if (tid == 7) sK = s;
    }
    __syncthreads();

    int pos = sWE[warp] + incl - cnt;
#pragma unroll
    for (int i = 0; i < 16; i++)
        if (av[i] > 0.f) sInd[pos++] = tid * 16 + i;
    __syncthreads();

    const int K = sK;

    float4 acc = make_float4(0.f, 0.f, 0.f, 0.f);
    if (tid < 128) {
        const int col = tid * 4;
        int j = 0;
        for (; j + 4 <= K; j += 4) {
            int i0 = sInd[j], i1 = sInd[j + 1], i2 = sInd[j + 2], i3 = sInd[j + 3];
            float4 v0 = *(const float4*)&Y[(size_t)i0 * HD + col];
            float4 v1 = *(const float4*)&Y[(size_t)i1 * HD + col];
            float4 v2 = *(const float4*)&Y[(size_t)i2 * HD + col];
            float4 v3 = *(const float4*)&Y[(size_t)i3 * HD + col];
            acc.x += v0.x + v1.x + v2.x + v3.x;
            acc.y += v0.y + v1.y + v2.y + v3.y;
            acc.z += v0.z + v1.z + v2.z + v3.z;
            acc.w += v0.w + v1.w + v2.w + v3.w;
        }
        for (; j < K; j++) {
            float4 v = *(const float4*)&Y[(size_t)sInd[j] * HD + col];
            acc.x += v.x; acc.y += v.y; acc.z += v.z; acc.w += v.w;
        }
    } else if (tid < 136) {
        const int h = tid - 128;
        float d = 0.f;
        int j = 0;
        for (; j + 4 <= K; j += 4) {
            d += ez[sInd[j] * HH + h] + ez[sInd[j + 1] * HH + h]
               + ez[sInd[j + 2] * HH + h] + ez[sInd[j + 3] * HH + h];
        }
        for (; j < K; j++) d += ez[sInd[j] * HH + h];
        sDen[h] = d;
    }
    __syncthreads();

    if (tid < 128) {
        const int col = tid * 4;
        float inv = 1.f / sDen[tid >> 4];
        acc.x *= inv; acc.y *= inv; acc.z *= inv; acc.w *= inv;
        *(float4*)&out[(size_t)node * HD + col] = acc;
    }
}

// ---------------------------------------------------------------------------
// inputs: 0:x  1:adj  2:W  3:a_origin (cancels)  4:a_dst
// ---------------------------------------------------------------------------
extern "C" void kernel_launch(void* const* d_in, const int* in_sizes, int n_in,
                              void* d_out, int out_size)
{
    const float* x     = (const float*)d_in[0];
    const float* adj   = (const float*)d_in[1];
    const float* W     = (const float*)d_in[2];
    const float* a_dst = (const float*)d_in[4];
    float* out = (float*)d_out;

    float* mx; cudaGetSymbolAddress((void**)&mx, g_mx);
    float* ez; cudaGetSymbolAddress((void**)&ez, g_ez);
    __nv_bfloat16 *xh, *xl, *wh, *wl;
    cudaGetSymbolAddress((void**)&xh, g_xh);
    cudaGetSymbolAddress((void**)&xl, g_xl);
    cudaGetSymbolAddress((void**)&wh, g_wh);
    cudaGetSymbolAddress((void**)&wl, g_wl);

    cudaFuncSetAttribute(gemm_mma_kernel,
                         cudaFuncAttributeMaxDynamicSharedMemorySize, GSMEM);

    conv_x_kernel<<<(NN * FIN / 4 + 255) / 256, 256>>>(x, xh, xl);
    conv_w_kernel<<<(HD * FIN + 255) / 256, 256>>>(W, wh, wl);

    dim3 ggrid(HD / 64, NN / 128);   // (8, 32) = 256 CTAs
    gemm_mma_kernel<<<ggrid, 256, GSMEM>>>(xh, xl, wh, wl, mx);

    prep_kernel<<<(NN * 32 + 255) / 256, 256>>>(mx, a_dst, ez);

    attn_kernel<<<NN, 256>>>(adj, mx, ez, out);
}

// round 12
// speedup vs baseline: 2.0170x; 1.0435x over previous
#include <cuda_runtime.h>
#include <cuda_bf16.h>
#include <cstdint>

#define NN   4096
#define FIN  512
#define HH   8
#define DD   64
#define HD   512

// Scratch (device globals)
__device__ float g_mx[NN * HD];          // pre-scaled Y = exp(t)*mx (8 MB)
__device__ float g_ez[NN * HH];          // exp(t)
__device__ __nv_bfloat16 g_xh[NN * FIN];
__device__ __nv_bfloat16 g_xl[NN * FIN];
__device__ __nv_bfloat16 g_wh[HD * FIN]; // W^T hi [n=h*64+d][k]
__device__ __nv_bfloat16 g_wl[HD * FIN];

__device__ __forceinline__ uint32_t smem_u32(const void* p) {
    uint32_t a;
    asm("{ .reg .u64 t; cvta.to.shared.u64 t, %1; cvt.u32.u64 %0, t; }" : "=r"(a) : "l"(p));
    return a;
}
__device__ __forceinline__ void ldsm4(uint32_t* r, uint32_t addr) {
    asm volatile("ldmatrix.sync.aligned.m8n8.x4.shared.b16 {%0,%1,%2,%3}, [%4];"
                 : "=r"(r[0]), "=r"(r[1]), "=r"(r[2]), "=r"(r[3]) : "r"(addr));
}
__device__ __forceinline__ void mma16816(float* c, const uint32_t* a, const uint32_t* b) {
    asm volatile(
        "mma.sync.aligned.m16n8k16.row.col.f32.bf16.bf16.f32 "
        "{%0,%1,%2,%3}, {%4,%5,%6,%7}, {%8,%9}, {%0,%1,%2,%3};"
        : "+f"(c[0]), "+f"(c[1]), "+f"(c[2]), "+f"(c[3])
        : "r"(a[0]), "r"(a[1]), "r"(a[2]), "r"(a[3]), "r"(b[0]), "r"(b[1]));
}

// ---------------------------------------------------------------------------
// Kernel 0: combined conversion. Blocks [0,2048): x hi/lo. [2048,3072): W^T hi/lo.
// ---------------------------------------------------------------------------
__global__ void conv_kernel(const float* __restrict__ x, const float* __restrict__ W,
                            __nv_bfloat16* __restrict__ xh, __nv_bfloat16* __restrict__ xl,
                            __nv_bfloat16* __restrict__ wh, __nv_bfloat16* __restrict__ wl) {
    int b = blockIdx.x;
    if (b < 2048) {
        int i = (b * 256 + threadIdx.x) * 4;
        float4 v = *(const float4*)(x + i);
        float f[4] = {v.x, v.y, v.z, v.w};
#pragma unroll
        for (int j = 0; j < 4; j++) {
            __nv_bfloat16 h = __float2bfloat16(f[j]);
            xh[i + j] = h;
            xl[i + j] = __float2bfloat16(f[j] - __bfloat162float(h));
        }
    } else {
        int i = (b - 2048) * 256 + threadIdx.x;   // < HD*FIN
        int n = i >> 9, k = i & 511;
        int h = n >> 6, d = n & 63;
        float w = W[h * FIN * DD + k * DD + d];
        __nv_bfloat16 hi = __float2bfloat16(w);
        wh[i] = hi;
        wl[i] = __float2bfloat16(w - __bfloat162float(hi));
    }
}

// ---------------------------------------------------------------------------
// Kernel 1: bf16-split GEMM (HMMA) + FUSED prep epilogue.
// CTA 128x64 (one head per CTA col block): compute t = mx . a_dst in-register,
// scale accumulators by exp(t), store Y and ez. No separate prep pass.
// ---------------------------------------------------------------------------
#define SROW 40
#define A_BYTES (128 * SROW * 2)
#define B_BYTES (64 * SROW * 2)
#define STAGE_BYTES (2 * A_BYTES + 2 * B_BYTES)
#define GSMEM (2 * STAGE_BYTES)
#define SOFF_AH 0
#define SOFF_AL A_BYTES
#define SOFF_BH (2 * A_BYTES)
#define SOFF_BL (2 * A_BYTES + B_BYTES)

__global__ __launch_bounds__(256) void gemm_mma_kernel(
    const __nv_bfloat16* __restrict__ xh, const __nv_bfloat16* __restrict__ xl,
    const __nv_bfloat16* __restrict__ wh, const __nv_bfloat16* __restrict__ wl,
    const float* __restrict__ a_dst,
    float* __restrict__ C, float* __restrict__ ez)
{
    extern __shared__ char sm[];
    const uint32_t sb = smem_u32(sm);
    const int tid = threadIdx.x;
    const int lane = tid & 31;
    const int warp = tid >> 5;
    const int wm = warp >> 1;
    const int wn = warp & 1;
    const int rowBase = blockIdx.y * 128;
    const int colBase = blockIdx.x * 64;   // head h = blockIdx.x

    const int ar = tid >> 1;
    const int ak = (tid & 1) * 16;
    const int br = tid >> 2;
    const int bk = (tid & 3) * 8;

    const __nv_bfloat16* gAh = xh + (size_t)(rowBase + ar) * FIN + ak;
    const __nv_bfloat16* gAl = xl + (size_t)(rowBase + ar) * FIN + ak;
    const __nv_bfloat16* gBh = wh + (size_t)(colBase + br) * FIN + bk;
    const __nv_bfloat16* gBl = wl + (size_t)(colBase + br) * FIN + bk;

    const uint32_t sAoff = (uint32_t)(ar * SROW + ak) * 2;
    const uint32_t sBoff = (uint32_t)(br * SROW + bk) * 2;

    float acc[2][4][4];
#pragma unroll
    for (int m = 0; m < 2; m++)
#pragma unroll
        for (int nb = 0; nb < 4; nb++)
#pragma unroll
            for (int q = 0; q < 4; q++) acc[m][nb][q] = 0.f;

    const int t  = lane >> 3;
    const int tr = lane & 7;
    const int a_mOff = (t & 1) * 8, a_kOff = (t >> 1) * 8;
    const int b_nOff = (t >> 1) * 8, b_kOff = (t & 1) * 8;

    {
        char* st = sm;
        *(uint4*)(st + SOFF_AH + sAoff)      = *(const uint4*)(gAh);
        *(uint4*)(st + SOFF_AH + sAoff + 16) = *(const uint4*)(gAh + 8);
        *(uint4*)(st + SOFF_AL + sAoff)      = *(const uint4*)(gAl);
        *(uint4*)(st + SOFF_AL + sAoff + 16) = *(const uint4*)(gAl + 8);
        *(uint4*)(st + SOFF_BH + sBoff)      = *(const uint4*)(gBh);
        *(uint4*)(st + SOFF_BL + sBoff)      = *(const uint4*)(gBl);
    }
    __syncthreads();

    for (int it = 0; it < 16; it++) {
        const int cur = it & 1;
        uint4 pA0, pA1, pAl0, pAl1, pB, pBl;
        if (it < 15) {
            int k0 = (it + 1) * 32;
            pA0  = *(const uint4*)(gAh + k0);
            pA1  = *(const uint4*)(gAh + k0 + 8);
            pAl0 = *(const uint4*)(gAl + k0);
            pAl1 = *(const uint4*)(gAl + k0 + 8);
            pB   = *(const uint4*)(gBh + k0);
            pBl  = *(const uint4*)(gBl + k0);
        }

        const uint32_t base = sb + (uint32_t)cur * STAGE_BYTES;
#pragma unroll
        for (int ks = 0; ks < 2; ks++) {
            uint32_t ah[2][4], al[2][4], bhf[4][2], blf[4][2];
#pragma unroll
            for (int m = 0; m < 2; m++) {
                uint32_t rowA = (uint32_t)(wm * 32 + m * 16 + a_mOff + tr);
                uint32_t colA = (uint32_t)(ks * 16 + a_kOff);
                uint32_t ad = base + (rowA * SROW + colA) * 2;
                ldsm4(ah[m], ad + SOFF_AH);
                ldsm4(al[m], ad + SOFF_AL);
            }
#pragma unroll
            for (int nb16 = 0; nb16 < 2; nb16++) {
                uint32_t rowB = (uint32_t)(wn * 32 + nb16 * 16 + b_nOff + tr);
                uint32_t colB = (uint32_t)(ks * 16 + b_kOff);
                uint32_t bd = base + (rowB * SROW + colB) * 2;
                uint32_t rh[4], rl[4];
                ldsm4(rh, bd + SOFF_BH);
                ldsm4(rl, bd + SOFF_BL);
                bhf[nb16 * 2 + 0][0] = rh[0]; bhf[nb16 * 2 + 0][1] = rh[1];
                bhf[nb16 * 2 + 1][0] = rh[2]; bhf[nb16 * 2 + 1][1] = rh[3];
                blf[nb16 * 2 + 0][0] = rl[0]; blf[nb16 * 2 + 0][1] = rl[1];
                blf[nb16 * 2 + 1][0] = rl[2]; blf[nb16 * 2 + 1][1] = rl[3];
            }
#pragma unroll
            for (int m = 0; m < 2; m++)
#pragma unroll
                for (int nb = 0; nb < 4; nb++) {
                    mma16816(acc[m][nb], ah[m], bhf[nb]);
                    mma16816(acc[m][nb], ah[m], blf[nb]);
                    mma16816(acc[m][nb], al[m], bhf[nb]);
                }
        }
        __syncthreads();

        if (it < 15) {
            char* st = sm + ((it + 1) & 1) * STAGE_BYTES;
            *(uint4*)(st + SOFF_AH + sAoff)      = pA0;
            *(uint4*)(st + SOFF_AH + sAoff + 16) = pA1;
            *(uint4*)(st + SOFF_AL + sAoff)      = pAl0;
            *(uint4*)(st + SOFF_AL + sAoff + 16) = pAl1;
            *(uint4*)(st + SOFF_BH + sBoff)      = pB;
            *(uint4*)(st + SOFF_BL + sBoff)      = pBl;
            __syncthreads();
        }
    }

    // ---- fused prep epilogue ----
    // acc layout: c[0],c[1] -> row (wm*32+m*16 + g), cols 2tg, 2tg+1 (+ nb*8 + wn*32)
    //             c[2],c[3] -> row +8
    const int g = lane >> 2, tg = lane & 3;
    const float* adv = a_dst + blockIdx.x * 64;

    float tp0[2] = {0.f, 0.f};   // per m: rows g-half
    float tp1[2] = {0.f, 0.f};   // per m: rows g+8-half
#pragma unroll
    for (int m = 0; m < 2; m++)
#pragma unroll
        for (int nb = 0; nb < 4; nb++) {
            float2 a2 = *(const float2*)&adv[wn * 32 + nb * 8 + 2 * tg];
            tp0[m] += acc[m][nb][0] * a2.x + acc[m][nb][1] * a2.y;
            tp1[m] += acc[m][nb][2] * a2.x + acc[m][nb][3] * a2.y;
        }
    // reduce across the quad (tg = lane bits 0..1)
#pragma unroll
    for (int off = 1; off < 4; off <<= 1) {
#pragma unroll
        for (int m = 0; m < 2; m++) {
            tp0[m] += __shfl_xor_sync(0xffffffffu, tp0[m], off);
            tp1[m] += __shfl_xor_sync(0xffffffffu, tp1[m], off);
        }
    }

    float* sT = (float*)sm;      // reuse stage smem: [2][128]
    if (tg == 0) {
#pragma unroll
        for (int m = 0; m < 2; m++) {
            sT[wn * 128 + wm * 32 + m * 16 + g]     = tp0[m];
            sT[wn * 128 + wm * 32 + m * 16 + g + 8] = tp1[m];
        }
    }
    __syncthreads();

#pragma unroll
    for (int m = 0; m < 2; m++) {
        int rl0 = wm * 32 + m * 16 + g;
        int row0 = rowBase + rl0;
        float e0 = __expf(sT[rl0] + sT[128 + rl0]);
        float e1 = __expf(sT[rl0 + 8] + sT[128 + rl0 + 8]);
        if (wn == 0 && tg == 0) {
            ez[(size_t)row0 * HH + blockIdx.x]       = e0;
            ez[(size_t)(row0 + 8) * HH + blockIdx.x] = e1;
        }
#pragma unroll
        for (int nb = 0; nb < 4; nb++) {
            int col = colBase + wn * 32 + nb * 8 + 2 * tg;
            *(float2*)&C[(size_t)row0 * HD + col] =
                make_float2(acc[m][nb][0] * e0, acc[m][nb][1] * e0);
            *(float2*)&C[(size_t)(row0 + 8) * HD + col] =
                make_float2(acc[m][nb][2] * e1, acc[m][nb][3] * e1);
        }
    }
}

// ---------------------------------------------------------------------------
// Kernel 2: sparse attention gather (uniform barriers).
// ---------------------------------------------------------------------------
__global__ __launch_bounds__(256) void attn_kernel(
    const float* __restrict__ adj, const float* __restrict__ Y,
    const float* __restrict__ ez, float* __restrict__ out)
{
    const int node = blockIdx.x;
    const int tid = threadIdx.x;
    const int lane = tid & 31;
    const int warp = tid >> 5;

    __shared__ int   sInd[NN];
    __shared__ int   sWS[8];
    __shared__ int   sWE[8];
    __shared__ int   sK;
    __shared__ float sDen[8];

    const float* row = adj + (size_t)node * NN;
    float av[16];
#pragma unroll
    for (int q = 0; q < 4; q++) {
        float4 v = *(const float4*)&row[tid * 16 + q * 4];
        av[q * 4 + 0] = v.x; av[q * 4 + 1] = v.y; av[q * 4 + 2] = v.z; av[q * 4 + 3] = v.w;
    }
    int cnt = 0;
#pragma unroll
    for (int i = 0; i < 16; i++) cnt += (av[i] > 0.f);

    int incl = cnt;
#pragma unroll
    for (int off = 1; off < 32; off <<= 1) {
        int v = __shfl_up_sync(0xffffffffu, incl, off);
        if (lane >= off) incl += v;
    }
    if (lane == 31) sWS[warp] = incl;
    __syncthreads();
    if (tid < 8) {
        int v = sWS[tid];
        int s = v;
#pragma unroll
        for (int off = 1; off < 8; off <<= 1) {
            int u = __shfl_up_sync(0xffu, s, off);
            if (tid >= off) s += u;
        }
        sWE[tid] = s - v;
        if (tid == 7) sK = s;
    }
    __syncthreads();

    int pos = sWE[warp] + incl - cnt;
#pragma unroll
    for (int i = 0; i < 16; i++)
        if (av[i] > 0.f) sInd[pos++] = tid * 16 + i;
    __syncthreads();

    const int K = sK;

    float4 acc = make_float4(0.f, 0.f, 0.f, 0.f);
    if (tid < 128) {
        const int col = tid * 4;
        int j = 0;
        for (; j + 4 <= K; j += 4) {
            int i0 = sInd[j], i1 = sInd[j + 1], i2 = sInd[j + 2], i3 = sInd[j + 3];
            float4 v0 = *(const float4*)&Y[(size_t)i0 * HD + col];
            float4 v1 = *(const float4*)&Y[(size_t)i1 * HD + col];
            float4 v2 = *(const float4*)&Y[(size_t)i2 * HD + col];
            float4 v3 = *(const float4*)&Y[(size_t)i3 * HD + col];
            acc.x += v0.x + v1.x + v2.x + v3.x;
            acc.y += v0.y + v1.y + v2.y + v3.y;
            acc.z += v0.z + v1.z + v2.z + v3.z;
            acc.w += v0.w + v1.w + v2.w + v3.w;
        }
        for (; j < K; j++) {
            float4 v = *(const float4*)&Y[(size_t)sInd[j] * HD + col];
            acc.x += v.x; acc.y += v.y; acc.z += v.z; acc.w += v.w;
        }
    } else if (tid < 136) {
        const int h = tid - 128;
        float d = 0.f;
        int j = 0;
        for (; j + 4 <= K; j += 4) {
            d += ez[sInd[j] * HH + h] + ez[sInd[j + 1] * HH + h]
               + ez[sInd[j + 2] * HH + h] + ez[sInd[j + 3] * HH + h];
        }
        for (; j < K; j++) d += ez[sInd[j] * HH + h];
        sDen[h] = d;
    }
    __syncthreads();

    if (tid < 128) {
        const int col = tid * 4;
        float inv = 1.f / sDen[tid >> 4];
        acc.x *= inv; acc.y *= inv; acc.z *= inv; acc.w *= inv;
        *(float4*)&out[(size_t)node * HD + col] = acc;
    }
}

// ---------------------------------------------------------------------------
// inputs: 0:x  1:adj  2:W  3:a_origin (cancels)  4:a_dst
// ---------------------------------------------------------------------------
extern "C" void kernel_launch(void* const* d_in, const int* in_sizes, int n_in,
                              void* d_out, int out_size)
{
    const float* x     = (const float*)d_in[0];
    const float* adj   = (const float*)d_in[1];
    const float* W     = (const float*)d_in[2];
    const float* a_dst = (const float*)d_in[4];
    float* out = (float*)d_out;

    float* mx; cudaGetSymbolAddress((void**)&mx, g_mx);
    float* ez; cudaGetSymbolAddress((void**)&ez, g_ez);
    __nv_bfloat16 *xh, *xl, *wh, *wl;
    cudaGetSymbolAddress((void**)&xh, g_xh);
    cudaGetSymbolAddress((void**)&xl, g_xl);
    cudaGetSymbolAddress((void**)&wh, g_wh);
    cudaGetSymbolAddress((void**)&wl, g_wl);

    cudaFuncSetAttribute(gemm_mma_kernel,
                         cudaFuncAttributeMaxDynamicSharedMemorySize, GSMEM);

    conv_kernel<<<3072, 256>>>(x, W, xh, xl, wh, wl);

    dim3 ggrid(HD / 64, NN / 128);   // (8, 32) = 256 CTAs
    gemm_mma_kernel<<<ggrid, 256, GSMEM>>>(xh, xl, wh, wl, a_dst, mx, ez);

    attn_kernel<<<NN, 256>>>(adj, mx, ez, out);
}

// round 14
// speedup vs baseline: 2.3592x; 1.1697x over previous
#include <cuda_runtime.h>
#include <cuda_bf16.h>
#include <cuda_fp16.h>
#include <cstdint>

#define NN   4096
#define FIN  512
#define HH   8
#define DD   64
#define HD   512

// Scratch (device globals)
__device__ __half g_Y[NN * HD];          // pre-scaled Y = exp(t)*mx, fp16 (4 MB)
__device__ float g_ez[NN * HH];          // exp(t) fp32
__device__ __nv_bfloat16 g_wh[HD * FIN]; // W^T hi [n=h*64+d][k]
__device__ __nv_bfloat16 g_wl[HD * FIN];

__device__ __forceinline__ uint32_t smem_u32(const void* p) {
    uint32_t a;
    asm("{ .reg .u64 t; cvta.to.shared.u64 t, %1; cvt.u32.u64 %0, t; }" : "=r"(a) : "l"(p));
    return a;
}
__device__ __forceinline__ void ldsm4(uint32_t* r, uint32_t addr) {
    asm volatile("ldmatrix.sync.aligned.m8n8.x4.shared.b16 {%0,%1,%2,%3}, [%4];"
                 : "=r"(r[0]), "=r"(r[1]), "=r"(r[2]), "=r"(r[3]) : "r"(addr));
}
__device__ __forceinline__ void mma16816(float* c, const uint32_t* a, const uint32_t* b) {
    asm volatile(
        "mma.sync.aligned.m16n8k16.row.col.f32.bf16.bf16.f32 "
        "{%0,%1,%2,%3}, {%4,%5,%6,%7}, {%8,%9}, {%0,%1,%2,%3};"
        : "+f"(c[0]), "+f"(c[1]), "+f"(c[2]), "+f"(c[3])
        : "r"(a[0]), "r"(a[1]), "r"(a[2]), "r"(a[3]), "r"(b[0]), "r"(b[1]));
}

// split 16 fp32 -> 8x packed bf16 hi + 8x packed bf16 lo
__device__ __forceinline__ void split16(const float* f, uint32_t* hi, uint32_t* lo) {
#pragma unroll
    for (int p = 0; p < 8; p++) {
        float f0 = f[2 * p], f1 = f[2 * p + 1];
        uint32_t h;
        asm("cvt.rn.bf16x2.f32 %0, %1, %2;" : "=r"(h) : "f"(f1), "f"(f0));
        float h0 = __uint_as_float(h << 16);
        float h1 = __uint_as_float(h & 0xFFFF0000u);
        float l0 = f0 - h0, l1 = f1 - h1;
        uint32_t l;
        asm("cvt.rn.bf16x2.f32 %0, %1, %2;" : "=r"(l) : "f"(l1), "f"(l0));
        hi[p] = h; lo[p] = l;
    }
}

// ---------------------------------------------------------------------------
// Kernel 0: W [H][F][D] -> W^T hi/lo [n=h*64+d][k], smem transpose.
// 128 blocks: h = b>>4, kb = (b&15)*32. 256 threads.
// ---------------------------------------------------------------------------
__global__ void convw_kernel(const float* __restrict__ W,
                             __nv_bfloat16* __restrict__ wh, __nv_bfloat16* __restrict__ wl) {
    __shared__ __nv_bfloat16 shh[64][48];
    __shared__ __nv_bfloat16 shl[64][48];
    const int h = blockIdx.x >> 4;
    const int kb = (blockIdx.x & 15) * 32;
    const int idx = threadIdx.x * 8;          // 0..2040
    const int kk = idx >> 6;                  // 0..31
    const int d0 = idx & 63;
    const float* src = W + (size_t)h * FIN * DD + (size_t)(kb + kk) * DD + d0;
    float f[8];
    *(float4*)&f[0] = *(const float4*)src;
    *(float4*)&f[4] = *(const float4*)(src + 4);
#pragma unroll
    for (int e = 0; e < 8; e++) {
        __nv_bfloat16 hi = __float2bfloat16(f[e]);
        shh[d0 + e][kk] = hi;
        shl[d0 + e][kk] = __float2bfloat16(f[e] - __bfloat162float(hi));
    }
    __syncthreads();
    const int dd = threadIdx.x >> 2;
    const int ck = (threadIdx.x & 3) * 8;
    size_t o = (size_t)(h * 64 + dd) * FIN + kb + ck;
    *(uint4*)&wh[o] = *(uint4*)&shh[dd][ck];
    *(uint4*)&wl[o] = *(uint4*)&shl[dd][ck];
}

// ---------------------------------------------------------------------------
// Kernel 1: bf16-split GEMM (HMMA) with in-loader x split + fused prep
// epilogue; Y stored as fp16.
// ---------------------------------------------------------------------------
#define SROW 40
#define A_BYTES (128 * SROW * 2)
#define B_BYTES (64 * SROW * 2)
#define STAGE_BYTES (2 * A_BYTES + 2 * B_BYTES)
#define GSMEM (2 * STAGE_BYTES)
#define SOFF_AH 0
#define SOFF_AL A_BYTES
#define SOFF_BH (2 * A_BYTES)
#define SOFF_BL (2 * A_BYTES + B_BYTES)

__global__ __launch_bounds__(256) void gemm_mma_kernel(
    const float* __restrict__ x,
    const __nv_bfloat16* __restrict__ wh, const __nv_bfloat16* __restrict__ wl,
    const float* __restrict__ a_dst,
    __half* __restrict__ Y, float* __restrict__ ez)
{
    extern __shared__ char sm[];
    const uint32_t sb = smem_u32(sm);
    const int tid = threadIdx.x;
    const int lane = tid & 31;
    const int warp = tid >> 5;
    const int wm = warp >> 1;
    const int wn = warp & 1;
    const int rowBase = blockIdx.y * 128;
    const int colBase = blockIdx.x * 64;   // head = blockIdx.x

    const int ar = tid >> 1;
    const int ak = (tid & 1) * 16;         // 16 floats per thread
    const int br = tid >> 2;
    const int bk = (tid & 3) * 8;

    const float* gA = x + (size_t)(rowBase + ar) * FIN + ak;
    const __nv_bfloat16* gBh = wh + (size_t)(colBase + br) * FIN + bk;
    const __nv_bfloat16* gBl = wl + (size_t)(colBase + br) * FIN + bk;

    const uint32_t sAoff = (uint32_t)(ar * SROW + ak) * 2;
    const uint32_t sBoff = (uint32_t)(br * SROW + bk) * 2;

    float acc[2][4][4];
#pragma unroll
    for (int m = 0; m < 2; m++)
#pragma unroll
        for (int nb = 0; nb < 4; nb++)
#pragma unroll
            for (int q = 0; q < 4; q++) acc[m][nb][q] = 0.f;

    const int t  = lane >> 3;
    const int tr = lane & 7;
    const int a_mOff = (t & 1) * 8, a_kOff = (t >> 1) * 8;
    const int b_nOff = (t >> 1) * 8, b_kOff = (t & 1) * 8;

    // ---- prologue: fill stage 0 (convert x fp32 -> bf16 hi/lo) ----
    {
        char* st = sm;
        float f[16];
        *(float4*)&f[0]  = *(const float4*)(gA + 0);
        *(float4*)&f[4]  = *(const float4*)(gA + 4);
        *(float4*)&f[8]  = *(const float4*)(gA + 8);
        *(float4*)&f[12] = *(const float4*)(gA + 12);
        uint32_t hi[8], lo[8];
        split16(f, hi, lo);
        *(uint4*)(st + SOFF_AH + sAoff)      = make_uint4(hi[0], hi[1], hi[2], hi[3]);
        *(uint4*)(st + SOFF_AH + sAoff + 16) = make_uint4(hi[4], hi[5], hi[6], hi[7]);
        *(uint4*)(st + SOFF_AL + sAoff)      = make_uint4(lo[0], lo[1], lo[2], lo[3]);
        *(uint4*)(st + SOFF_AL + sAoff + 16) = make_uint4(lo[4], lo[5], lo[6], lo[7]);
        *(uint4*)(st + SOFF_BH + sBoff)      = *(const uint4*)(gBh);
        *(uint4*)(st + SOFF_BL + sBoff)      = *(const uint4*)(gBl);
    }
    __syncthreads();

    for (int it = 0; it < 16; it++) {
        const int cur = it & 1;
        float pf[16];
        uint4 pB, pBl;
        if (it < 15) {
            int k0 = (it + 1) * 32;
            *(float4*)&pf[0]  = *(const float4*)(gA + k0);
            *(float4*)&pf[4]  = *(const float4*)(gA + k0 + 4);
            *(float4*)&pf[8]  = *(const float4*)(gA + k0 + 8);
            *(float4*)&pf[12] = *(const float4*)(gA + k0 + 12);
            pB  = *(const uint4*)(gBh + k0);
            pBl = *(const uint4*)(gBl + k0);
        }

        const uint32_t base = sb + (uint32_t)cur * STAGE_BYTES;
#pragma unroll
        for (int ks = 0; ks < 2; ks++) {
            uint32_t ah[2][4], al[2][4], bhf[4][2], blf[4][2];
#pragma unroll
            for (int m = 0; m < 2; m++) {
                uint32_t rowA = (uint32_t)(wm * 32 + m * 16 + a_mOff + tr);
                uint32_t colA = (uint32_t)(ks * 16 + a_kOff);
                uint32_t ad = base + (rowA * SROW + colA) * 2;
                ldsm4(ah[m], ad + SOFF_AH);
                ldsm4(al[m], ad + SOFF_AL);
            }
#pragma unroll
            for (int nb16 = 0; nb16 < 2; nb16++) {
                uint32_t rowB = (uint32_t)(wn * 32 + nb16 * 16 + b_nOff + tr);
                uint32_t colB = (uint32_t)(ks * 16 + b_kOff);
                uint32_t bd = base + (rowB * SROW + colB) * 2;
                uint32_t rh[4], rl[4];
                ldsm4(rh, bd + SOFF_BH);
                ldsm4(rl, bd + SOFF_BL);
                bhf[nb16 * 2 + 0][0] = rh[0]; bhf[nb16 * 2 + 0][1] = rh[1];
                bhf[nb16 * 2 + 1][0] = rh[2]; bhf[nb16 * 2 + 1][1] = rh[3];
                blf[nb16 * 2 + 0][0] = rl[0]; blf[nb16 * 2 + 0][1] = rl[1];
                blf[nb16 * 2 + 1][0] = rl[2]; blf[nb16 * 2 + 1][1] = rl[3];
            }
#pragma unroll
            for (int m = 0; m < 2; m++)
#pragma unroll
                for (int nb = 0; nb < 4; nb++) {
                    mma16816(acc[m][nb], ah[m], bhf[nb]);
                    mma16816(acc[m][nb], ah[m], blf[nb]);
                    mma16816(acc[m][nb], al[m], bhf[nb]);
                }
        }
        __syncthreads();

        if (it < 15) {
            char* st = sm + ((it + 1) & 1) * STAGE_BYTES;
            uint32_t hi[8], lo[8];
            split16(pf, hi, lo);
            *(uint4*)(st + SOFF_AH + sAoff)      = make_uint4(hi[0], hi[1], hi[2], hi[3]);
            *(uint4*)(st + SOFF_AH + sAoff + 16) = make_uint4(hi[4], hi[5], hi[6], hi[7]);
            *(uint4*)(st + SOFF_AL + sAoff)      = make_uint4(lo[0], lo[1], lo[2], lo[3]);
            *(uint4*)(st + SOFF_AL + sAoff + 16) = make_uint4(lo[4], lo[5], lo[6], lo[7]);
            *(uint4*)(st + SOFF_BH + sBoff)      = pB;
            *(uint4*)(st + SOFF_BL + sBoff)      = pBl;
            __syncthreads();
        }
    }

    // ---- fused prep epilogue ----
    const int g = lane >> 2, tg = lane & 3;
    const float* adv = a_dst + blockIdx.x * 64;

    float tp0[2] = {0.f, 0.f};
    float tp1[2] = {0.f, 0.f};
#pragma unroll
    for (int m = 0; m < 2; m++)
#pragma unroll
        for (int nb = 0; nb < 4; nb++) {
            float2 a2 = *(const float2*)&adv[wn * 32 + nb * 8 + 2 * tg];
            tp0[m] += acc[m][nb][0] * a2.x + acc[m][nb][1] * a2.y;
            tp1[m] += acc[m][nb][2] * a2.x + acc[m][nb][3] * a2.y;
        }
#pragma unroll
    for (int off = 1; off < 4; off <<= 1) {
#pragma unroll
        for (int m = 0; m < 2; m++) {
            tp0[m] += __shfl_xor_sync(0xffffffffu, tp0[m], off);
            tp1[m] += __shfl_xor_sync(0xffffffffu, tp1[m], off);
        }
    }

    float* sT = (float*)sm;      // reuse stage smem: [2][128]
    if (tg == 0) {
#pragma unroll
        for (int m = 0; m < 2; m++) {
            sT[wn * 128 + wm * 32 + m * 16 + g]     = tp0[m];
            sT[wn * 128 + wm * 32 + m * 16 + g + 8] = tp1[m];
        }
    }
    __syncthreads();

#pragma unroll
    for (int m = 0; m < 2; m++) {
        int rl0 = wm * 32 + m * 16 + g;
        int row0 = rowBase + rl0;
        float e0 = __expf(sT[rl0] + sT[128 + rl0]);
        float e1 = __expf(sT[rl0 + 8] + sT[128 + rl0 + 8]);
        if (wn == 0 && tg == 0) {
            ez[(size_t)row0 * HH + blockIdx.x]       = e0;
            ez[(size_t)(row0 + 8) * HH + blockIdx.x] = e1;
        }
#pragma unroll
        for (int nb = 0; nb < 4; nb++) {
            int col = colBase + wn * 32 + nb * 8 + 2 * tg;
            *(__half2*)&Y[(size_t)row0 * HD + col] =
                __floats2half2_rn(acc[m][nb][0] * e0, acc[m][nb][1] * e0);
            *(__half2*)&Y[(size_t)(row0 + 8) * HD + col] =
                __floats2half2_rn(acc[m][nb][2] * e1, acc[m][nb][3] * e1);
        }
    }
}

// ---------------------------------------------------------------------------
// Kernel 2: sparse attention gather over fp16 Y (uniform barriers).
// ---------------------------------------------------------------------------
__global__ __launch_bounds__(256) void attn_kernel(
    const float* __restrict__ adj, const __half* __restrict__ Y,
    const float* __restrict__ ez, float* __restrict__ out)
{
    const int node = blockIdx.x;
    const int tid = threadIdx.x;
    const int lane = tid & 31;
    const int warp = tid >> 5;

    __shared__ int   sInd[NN];
    __shared__ int   sWS[8];
    __shared__ int   sWE[8];
    __shared__ int   sK;
    __shared__ float sDen[8];

    const float* row = adj + (size_t)node * NN;
    float av[16];
#pragma unroll
    for (int q = 0; q < 4; q++) {
        float4 v = *(const float4*)&row[tid * 16 + q * 4];
        av[q * 4 + 0] = v.x; av[q * 4 + 1] = v.y; av[q * 4 + 2] = v.z; av[q * 4 + 3] = v.w;
    }
    int cnt = 0;
#pragma unroll
    for (int i = 0; i < 16; i++) cnt += (av[i] > 0.f);

    int incl = cnt;
#pragma unroll
    for (int off = 1; off < 32; off <<= 1) {
        int v = __shfl_up_sync(0xffffffffu, incl, off);
        if (lane >= off) incl += v;
    }
    if (lane == 31) sWS[warp] = incl;
    __syncthreads();
    if (tid < 8) {
        int v = sWS[tid];
        int s = v;
#pragma unroll
        for (int off = 1; off < 8; off <<= 1) {
            int u = __shfl_up_sync(0xffu, s, off);
            if (tid >= off) s += u;
        }
        sWE[tid] = s - v;
        if (tid == 7) sK = s;
    }
    __syncthreads();

    int pos = sWE[warp] + incl - cnt;
#pragma unroll
    for (int i = 0; i < 16; i++)
        if (av[i] > 0.f) sInd[pos++] = tid * 16 + i;
    __syncthreads();

    const int K = sK;

    float4 acc = make_float4(0.f, 0.f, 0.f, 0.f);
    if (tid < 128) {
        const int col = tid * 4;
        int j = 0;
        for (; j + 4 <= K; j += 4) {
#pragma unroll
            for (int u = 0; u < 4; u++) {
                uint2 v = *(const uint2*)&Y[(size_t)sInd[j + u] * HD + col];
                float2 p0 = __half22float2(*(const __half2*)&v.x);
                float2 p1 = __half22float2(*(const __half2*)&v.y);
                acc.x += p0.x; acc.y += p0.y; acc.z += p1.x; acc.w += p1.y;
            }
        }
        for (; j < K; j++) {
            uint2 v = *(const uint2*)&Y[(size_t)sInd[j] * HD + col];
            float2 p0 = __half22float2(*(const __half2*)&v.x);
            float2 p1 = __half22float2(*(const __half2*)&v.y);
            acc.x += p0.x; acc.y += p0.y; acc.z += p1.x; acc.w += p1.y;
        }
    } else if (tid < 136) {
        const int h = tid - 128;
        float d = 0.f;
        int j = 0;
        for (; j + 4 <= K; j += 4) {
            d += ez[sInd[j] * HH + h] + ez[sInd[j + 1] * HH + h]
               + ez[sInd[j + 2] * HH + h] + ez[sInd[j + 3] * HH + h];
        }
        for (; j < K; j++) d += ez[sInd[j] * HH + h];
        sDen[h] = d;
    }
    __syncthreads();

    if (tid < 128) {
        const int col = tid * 4;
        float inv = 1.f / sDen[tid >> 4];
        acc.x *= inv; acc.y *= inv; acc.z *= inv; acc.w *= inv;
        *(float4*)&out[(size_t)node * HD + col] = acc;
    }
}

// ---------------------------------------------------------------------------
// inputs: 0:x  1:adj  2:W  3:a_origin (cancels)  4:a_dst
// ---------------------------------------------------------------------------
extern "C" void kernel_launch(void* const* d_in, const int* in_sizes, int n_in,
                              void* d_out, int out_size)
{
    const float* x     = (const float*)d_in[0];
    const float* adj   = (const float*)d_in[1];
    const float* W     = (const float*)d_in[2];
    const float* a_dst = (const float*)d_in[4];
    float* out = (float*)d_out;

    __half* Y; cudaGetSymbolAddress((void**)&Y, g_Y);
    float* ez; cudaGetSymbolAddress((void**)&ez, g_ez);
    __nv_bfloat16 *wh, *wl;
    cudaGetSymbolAddress((void**)&wh, g_wh);
    cudaGetSymbolAddress((void**)&wl, g_wl);

    cudaFuncSetAttribute(gemm_mma_kernel,
                         cudaFuncAttributeMaxDynamicSharedMemorySize, GSMEM);

    convw_kernel<<<128, 256>>>(W, wh, wl);

    dim3 ggrid(HD / 64, NN / 128);   // (8, 32) = 256 CTAs
    gemm_mma_kernel<<<ggrid, 256, GSMEM>>>(x, wh, wl, a_dst, Y, ez);

    attn_kernel<<<NN, 256>>>(adj, Y, ez, out);
}